// round 2
// baseline (speedup 1.0000x reference)
#include <cuda_runtime.h>

// Problem: cumulative matrix product (associative scan of matmul) over axis 1.
// input:  (32, 256, 128, 128) fp32
// output: x (32,128,128) followed by all_outputs (32,256,128,128), flat.
//
// Chunked scan: L=16 chunk length, C=16 chunks per batch.
//  Pass1: per (batch,chunk) sequential local prefix products -> written into all_outputs slots
//  Pass2: Hillis-Steele scan over chunk totals (4 ping-pong steps, depth 4)
//  Pass3: out[b, c*L+j] = chunk_scan[b, c-1] @ local[b, c*L+j]  (in-place, c>=1)
//  Pass4: copy x = all_outputs[:, 255]

#define DN 128
#define BATCH 32
#define SEQ 256
#define CH 16   // number of chunks
#define CL 16   // chunk length
#define KS 16   // K slab for matmul tiling

// scratch for chunk-total scan (ping-pong), 33.5 MB each
__device__ float g_scr0[(size_t)BATCH * CH * DN * DN];
__device__ float g_scr1[(size_t)BATCH * CH * DN * DN];

__device__ __forceinline__ void copy128(const float* __restrict__ s, float* __restrict__ d) {
    const float4* s4 = (const float4*)s;
    float4* d4 = (float4*)d;
#pragma unroll
    for (int i = threadIdx.x; i < DN * DN / 4; i += 256) d4[i] = s4[i];
}

// Block of 256 threads computes C = A(128x128) @ B(128x128), row-major fp32.
// Cout may alias B (C is stored only after every thread's B loads complete,
// separated by the final __syncthreads inside the k-loop).
// A __syncthreads() at the top of each slab iteration also makes this safe to
// call in a loop where Cout of step j-1 is A of step j (same block).
__device__ __forceinline__ void mm128(const float* __restrict__ A,
                                      const float* __restrict__ B,
                                      float* __restrict__ Cout) {
    __shared__ float As[KS][DN + 4];  // [kk][m], padded to avoid conflicts + keep 16B align
    __shared__ float Bs[KS][DN];      // [kk][n]

    const int tid = threadIdx.x;
    const int tx = tid & 15;   // 0..15
    const int ty = tid >> 4;   // 0..15
    const int m0 = ty * 8;
    const int n0 = tx * 8;

    float acc[8][8];
#pragma unroll
    for (int i = 0; i < 8; i++)
#pragma unroll
        for (int j = 0; j < 8; j++) acc[i][j] = 0.0f;

    for (int k0 = 0; k0 < DN; k0 += KS) {
        __syncthreads();  // orders prior C stores (chain use) before new A loads
        // Load A slab transposed: As[kk][m] = A[m][k0+kk]
#pragma unroll
        for (int r = 0; r < DN; r += 16)
            As[tx][ty + r] = A[(size_t)(ty + r) * DN + k0 + tx];
        // Load B slab: Bs[kk][n] = B[k0+kk][n]  (perfectly coalesced float4)
        {
            const float4* Bv = (const float4*)(B + (size_t)k0 * DN);
            float4* Bs4 = (float4*)(&Bs[0][0]);
            Bs4[tid] = Bv[tid];
            Bs4[tid + 256] = Bv[tid + 256];
        }
        __syncthreads();
#pragma unroll
        for (int kk = 0; kk < KS; kk++) {
            float4 a0 = *(const float4*)&As[kk][m0];
            float4 a1 = *(const float4*)&As[kk][m0 + 4];
            float4 b0 = *(const float4*)&Bs[kk][n0];
            float4 b1 = *(const float4*)&Bs[kk][n0 + 4];
            float a[8] = {a0.x, a0.y, a0.z, a0.w, a1.x, a1.y, a1.z, a1.w};
            float b[8] = {b0.x, b0.y, b0.z, b0.w, b1.x, b1.y, b1.z, b1.w};
#pragma unroll
            for (int i = 0; i < 8; i++)
#pragma unroll
                for (int j = 0; j < 8; j++)
                    acc[i][j] = fmaf(a[i], b[j], acc[i][j]);
        }
    }

#pragma unroll
    for (int i = 0; i < 8; i++) {
        float4 v0 = {acc[i][0], acc[i][1], acc[i][2], acc[i][3]};
        float4 v1 = {acc[i][4], acc[i][5], acc[i][6], acc[i][7]};
        *(float4*)&Cout[(size_t)(m0 + i) * DN + n0] = v0;
        *(float4*)&Cout[(size_t)(m0 + i) * DN + n0 + 4] = v1;
    }
}

// Pass 1: local prefix products within each chunk (written into all_outputs).
__global__ void __launch_bounds__(256) k_pass1(const float* __restrict__ in,
                                               float* __restrict__ outAll) {
    const int b = blockIdx.x / CH;
    const int c = blockIdx.x % CH;
    const size_t base = ((size_t)b * SEQ + (size_t)c * CL) * (DN * DN);
    const float* E = in + base;
    float* O = outAll + base;
    copy128(E, O);  // local[0] = E[0]; mm128's first __syncthreads orders this
    for (int j = 1; j < CL; j++) {
        mm128(O + (size_t)(j - 1) * DN * DN,
              E + (size_t)j * DN * DN,
              O + (size_t)j * DN * DN);
    }
}

// Pass 2 step (Hillis-Steele over chunk totals): dst[b,i] = src[b,i-d] @ src[b,i]
// src addressed as src + soff + b*sb + i*si  (lets step 1 read totals in outAll).
__global__ void __launch_bounds__(256) k_scan(const float* __restrict__ src,
                                              size_t soff, size_t sb, size_t si,
                                              float* __restrict__ dst, int d) {
    const int b = blockIdx.x / CH;
    const int i = blockIdx.x % CH;
    const float* Ti = src + soff + (size_t)b * sb + (size_t)i * si;
    float* Dp = dst + ((size_t)b * CH + i) * (DN * DN);
    if (i < d) {
        copy128(Ti, Dp);
        return;
    }
    const float* Ta = src + soff + (size_t)b * sb + (size_t)(i - d) * si;
    mm128(Ta, Ti, Dp);
}

// Pass 3: apply exclusive chunk prefix to every element of chunks 1..CH-1 (in place).
__global__ void __launch_bounds__(256) k_pass3(float* __restrict__ outAll,
                                               const float* __restrict__ scan) {
    int idx = blockIdx.x;
    const int j = idx % CL; idx /= CL;
    const int c = (idx % (CH - 1)) + 1; idx /= (CH - 1);
    const int b = idx;
    const float* A = scan + ((size_t)b * CH + (c - 1)) * (DN * DN);
    float* Bp = outAll + ((size_t)b * SEQ + (size_t)c * CL + j) * (DN * DN);
    mm128(A, Bp, Bp);
}

// Pass 4: x[b] = all_outputs[b, SEQ-1]
__global__ void __launch_bounds__(256) k_copy_x(const float* __restrict__ outAll,
                                                float* __restrict__ x) {
    const int b = blockIdx.x;
    copy128(outAll + ((size_t)b * SEQ + (SEQ - 1)) * (DN * DN),
            x + (size_t)b * DN * DN);
}

extern "C" void kernel_launch(void* const* d_in, const int* in_sizes, int n_in,
                              void* d_out, int out_size) {
    const float* in = (const float*)d_in[0];
    float* out = (float*)d_out;
    float* x = out;                                  // first 32*128*128 elements
    float* outAll = out + (size_t)BATCH * DN * DN;   // then 32*256*128*128

    float *scr0, *scr1;
    cudaGetSymbolAddress((void**)&scr0, g_scr0);
    cudaGetSymbolAddress((void**)&scr1, g_scr1);

    const size_t MM = (size_t)DN * DN;

    k_pass1<<<BATCH * CH, 256>>>(in, outAll);
    // Hillis-Steele over chunk totals: totals live at element (c+1)*CL-1 of outAll
    k_scan<<<BATCH * CH, 256>>>(outAll, (size_t)(CL - 1) * MM,
                                (size_t)SEQ * MM, (size_t)CL * MM, scr0, 1);
    k_scan<<<BATCH * CH, 256>>>(scr0, 0, (size_t)CH * MM, MM, scr1, 2);
    k_scan<<<BATCH * CH, 256>>>(scr1, 0, (size_t)CH * MM, MM, scr0, 4);
    k_scan<<<BATCH * CH, 256>>>(scr0, 0, (size_t)CH * MM, MM, scr1, 8);
    k_pass3<<<BATCH * (CH - 1) * CL, 256>>>(outAll, scr1);
    k_copy_x<<<BATCH, 256>>>(outAll, x);
}

// round 3
// speedup vs baseline: 1.2754x; 1.2754x over previous
#include <cuda_runtime.h>

// Cumulative matrix product (associative scan of matmul) over axis 1.
// input:  (32, 256, 128, 128) fp32
// output: x (32,128,128) followed by all_outputs (32,256,128,128), flat.
//
// Chunked scan, matmul core = 3xTF32 tensor-core MMA (m16n8k8).

#define DN 128
#define BATCH 32
#define SEQ 256
#define CH 16   // number of chunks
#define CL 16   // chunk length
#define KS 16   // K slab

// scratch for chunk-total scan (ping-pong)
__device__ float g_scr0[(size_t)BATCH * CH * DN * DN];
__device__ float g_scr1[(size_t)BATCH * CH * DN * DN];

__device__ __forceinline__ void copy128(const float* __restrict__ s, float* __restrict__ d) {
    const float4* s4 = (const float4*)s;
    float4* d4 = (float4*)d;
#pragma unroll
    for (int i = threadIdx.x; i < DN * DN / 4; i += 256) d4[i] = s4[i];
}

__device__ __forceinline__ unsigned f2tf32(float x) {
    unsigned r;
    asm("cvt.rna.tf32.f32 %0, %1;" : "=r"(r) : "f"(x));
    return r;
}

__device__ __forceinline__ void mma8(float c[4], const unsigned a[4], const unsigned b[2]) {
    asm volatile(
        "mma.sync.aligned.m16n8k8.row.col.f32.tf32.tf32.f32 "
        "{%0,%1,%2,%3},{%4,%5,%6,%7},{%8,%9},{%0,%1,%2,%3};"
        : "+f"(c[0]), "+f"(c[1]), "+f"(c[2]), "+f"(c[3])
        : "r"(a[0]), "r"(a[1]), "r"(a[2]), "r"(a[3]), "r"(b[0]), "r"(b[1]));
}

// Block of 256 threads (8 warps): C = A(128x128) @ B(128x128), row-major fp32,
// 3xTF32 decomposition (hi*hi + lo*hi + hi*lo). Cout may alias B: all global B
// reads complete before the last __syncthreads; stores happen after. The
// leading __syncthreads in each slab iteration also makes chained calls
// (Cout of call j-1 used as A of call j) safe.
__device__ __forceinline__ void mm128(const float* __restrict__ A,
                                      const float* __restrict__ B,
                                      float* __restrict__ Cout) {
    __shared__ float As[DN][KS + 4];   // [m][k], stride 20 -> conflict-free frag loads
    __shared__ float Bs[KS][DN + 8];   // [k][n], stride 136 -> conflict-free frag loads

    const int tid = threadIdx.x;
    const int lane = tid & 31;
    const int w = tid >> 5;
    const int wm = (w >> 2) * 64;   // warp m origin (0 or 64)
    const int wn = (w & 3) * 32;    // warp n origin
    const int q = lane >> 2;        // 0..7
    const int kq = lane & 3;        // 0..3

    float acc[4][4][4];
#pragma unroll
    for (int mt = 0; mt < 4; mt++)
#pragma unroll
        for (int nt = 0; nt < 4; nt++)
#pragma unroll
            for (int i = 0; i < 4; i++) acc[mt][nt][i] = 0.0f;

    for (int k0 = 0; k0 < DN; k0 += KS) {
        __syncthreads();  // orders prior-chain C stores / prior slab consumption
        // Load A slab [128 x 16] as [m][k], float4 coalesced
        {
            int m = tid >> 2, c4 = (tid & 3) * 4;
            *(float4*)&As[m][c4] = *(const float4*)&A[(size_t)m * DN + k0 + c4];
            *(float4*)&As[m + 64][c4] = *(const float4*)&A[(size_t)(m + 64) * DN + k0 + c4];
        }
        // Load B slab [16 x 128] as [k][n], float4 coalesced
        {
            int r = tid >> 5, c4 = (tid & 31) * 4;
            *(float4*)&Bs[r][c4] = *(const float4*)&B[(size_t)(k0 + r) * DN + c4];
            *(float4*)&Bs[r + 8][c4] = *(const float4*)&B[(size_t)(k0 + r + 8) * DN + c4];
        }
        __syncthreads();

#pragma unroll
        for (int kk = 0; kk < KS; kk += 8) {
            // B fragments (col-major k8n8), hi/lo split, 4 n-tiles
            unsigned bh[4][2], bl[4][2];
#pragma unroll
            for (int nt = 0; nt < 4; nt++) {
                float b0 = Bs[kk + kq][wn + nt * 8 + q];
                float b1 = Bs[kk + kq + 4][wn + nt * 8 + q];
                bh[nt][0] = f2tf32(b0);
                bl[nt][0] = f2tf32(b0 - __uint_as_float(bh[nt][0]));
                bh[nt][1] = f2tf32(b1);
                bl[nt][1] = f2tf32(b1 - __uint_as_float(bh[nt][1]));
            }
#pragma unroll
            for (int mt = 0; mt < 4; mt++) {
                float a0 = As[wm + mt * 16 + q][kk + kq];
                float a1 = As[wm + mt * 16 + q + 8][kk + kq];
                float a2 = As[wm + mt * 16 + q][kk + kq + 4];
                float a3 = As[wm + mt * 16 + q + 8][kk + kq + 4];
                unsigned ah[4], al[4];
                ah[0] = f2tf32(a0); al[0] = f2tf32(a0 - __uint_as_float(ah[0]));
                ah[1] = f2tf32(a1); al[1] = f2tf32(a1 - __uint_as_float(ah[1]));
                ah[2] = f2tf32(a2); al[2] = f2tf32(a2 - __uint_as_float(ah[2]));
                ah[3] = f2tf32(a3); al[3] = f2tf32(a3 - __uint_as_float(ah[3]));
#pragma unroll
                for (int nt = 0; nt < 4; nt++) {
                    mma8(acc[mt][nt], ah, bh[nt]);
                    mma8(acc[mt][nt], al, bh[nt]);
                    mma8(acc[mt][nt], ah, bl[nt]);
                }
            }
        }
    }

    // Store C (after last sync: no thread reads B-global anymore -> alias-safe)
#pragma unroll
    for (int mt = 0; mt < 4; mt++)
#pragma unroll
        for (int nt = 0; nt < 4; nt++) {
            int r0 = wm + mt * 16 + q;
            int c0 = wn + nt * 8 + 2 * kq;
            *(float2*)&Cout[(size_t)r0 * DN + c0] = make_float2(acc[mt][nt][0], acc[mt][nt][1]);
            *(float2*)&Cout[(size_t)(r0 + 8) * DN + c0] = make_float2(acc[mt][nt][2], acc[mt][nt][3]);
        }
}

// Pass 1: local prefix products within each chunk (written into all_outputs).
__global__ void __launch_bounds__(256, 2) k_pass1(const float* __restrict__ in,
                                                  float* __restrict__ outAll) {
    const int b = blockIdx.x / CH;
    const int c = blockIdx.x % CH;
    const size_t base = ((size_t)b * SEQ + (size_t)c * CL) * (DN * DN);
    const float* E = in + base;
    float* O = outAll + base;
    copy128(E, O);
    for (int j = 1; j < CL; j++) {
        mm128(O + (size_t)(j - 1) * DN * DN,
              E + (size_t)j * DN * DN,
              O + (size_t)j * DN * DN);
    }
}

// Pass 2 step (Hillis-Steele over chunk totals): dst[b,i] = src[b,i-d] @ src[b,i]
__global__ void __launch_bounds__(256, 2) k_scan(const float* __restrict__ src,
                                                 size_t soff, size_t sb, size_t si,
                                                 float* __restrict__ dst, int d) {
    const int b = blockIdx.x / CH;
    const int i = blockIdx.x % CH;
    const float* Ti = src + soff + (size_t)b * sb + (size_t)i * si;
    float* Dp = dst + ((size_t)b * CH + i) * (DN * DN);
    if (i < d) {
        copy128(Ti, Dp);
        return;
    }
    const float* Ta = src + soff + (size_t)b * sb + (size_t)(i - d) * si;
    mm128(Ta, Ti, Dp);
}

// Pass 3: apply exclusive chunk prefix to chunks 1..CH-1 (in place).
__global__ void __launch_bounds__(256, 2) k_pass3(float* __restrict__ outAll,
                                                  const float* __restrict__ scan) {
    int idx = blockIdx.x;
    const int j = idx % CL; idx /= CL;
    const int c = (idx % (CH - 1)) + 1; idx /= (CH - 1);
    const int b = idx;
    const float* A = scan + ((size_t)b * CH + (c - 1)) * (DN * DN);
    float* Bp = outAll + ((size_t)b * SEQ + (size_t)c * CL + j) * (DN * DN);
    mm128(A, Bp, Bp);
}

// Pass 4: x[b] = all_outputs[b, SEQ-1]
__global__ void __launch_bounds__(256) k_copy_x(const float* __restrict__ outAll,
                                                float* __restrict__ x) {
    const int b = blockIdx.x;
    copy128(outAll + ((size_t)b * SEQ + (SEQ - 1)) * (DN * DN),
            x + (size_t)b * DN * DN);
}

extern "C" void kernel_launch(void* const* d_in, const int* in_sizes, int n_in,
                              void* d_out, int out_size) {
    const float* in = (const float*)d_in[0];
    float* out = (float*)d_out;
    float* x = out;                                  // first 32*128*128 elements
    float* outAll = out + (size_t)BATCH * DN * DN;   // then 32*256*128*128

    float *scr0, *scr1;
    cudaGetSymbolAddress((void**)&scr0, g_scr0);
    cudaGetSymbolAddress((void**)&scr1, g_scr1);

    const size_t MM = (size_t)DN * DN;

    k_pass1<<<BATCH * CH, 256>>>(in, outAll);
    // Hillis-Steele over chunk totals: totals live at element (c+1)*CL-1 of outAll
    k_scan<<<BATCH * CH, 256>>>(outAll, (size_t)(CL - 1) * MM,
                                (size_t)SEQ * MM, (size_t)CL * MM, scr0, 1);
    k_scan<<<BATCH * CH, 256>>>(scr0, 0, (size_t)CH * MM, MM, scr1, 2);
    k_scan<<<BATCH * CH, 256>>>(scr1, 0, (size_t)CH * MM, MM, scr0, 4);
    k_scan<<<BATCH * CH, 256>>>(scr0, 0, (size_t)CH * MM, MM, scr1, 8);
    k_pass3<<<BATCH * (CH - 1) * CL, 256>>>(outAll, scr1);
    k_copy_x<<<BATCH, 256>>>(outAll, x);
}